// round 10
// baseline (speedup 1.0000x reference)
#include <cuda_runtime.h>
#include <cstdint>

#define NTS    2048
#define KXV    256
#define NYV    8192
#define GSTEP  4            /* steps between cross-CTA exchanges */
#define GL     (4*GSTEP)    /* 16 left ghosts  */
#define GR     (8*GSTEP)    /* 32 right ghosts */
#define NG     (GL+GR)      /* 48 */
#define GBASE  256          /* ghost duty on threads [GBASE, GBASE+NG) */

__device__ __forceinline__ uint32_t s2u(const void* p){
    return (uint32_t)__cvta_generic_to_shared(p);
}
__device__ __forceinline__ uint32_t mapa_u32(uint32_t la, uint32_t rank){
    uint32_t ra;
    asm("mapa.shared::cluster.u32 %0, %1, %2;" : "=r"(ra) : "r"(la), "r"(rank));
    return ra;
}
__device__ __forceinline__ void mbar_init(uint32_t a, uint32_t cnt){
    asm volatile("mbarrier.init.shared.b64 [%0], %1;" :: "r"(a), "r"(cnt) : "memory");
}
__device__ __forceinline__ void remote_st(uint32_t ra, float v){
    asm volatile("st.shared::cluster.f32 [%0], %1;" :: "r"(ra), "f"(v) : "memory");
}
__device__ __forceinline__ void remote_arrive(uint32_t ra){
    asm volatile("mbarrier.arrive.release.cluster.shared::cluster.b64 _, [%0];"
                 :: "r"(ra) : "memory");
}
__device__ __forceinline__ void mbar_wait(uint32_t a, uint32_t parity){
    asm volatile(
        "{\n\t"
        ".reg .pred P;\n"
        "WL_%=:\n\t"
        "mbarrier.try_wait.parity.acquire.cluster.shared::cta.b64 P, [%0], %1;\n\t"
        "@!P bra WL_%=;\n\t"
        "}"
        :: "r"(a), "r"(parity) : "memory");
}

template<int CSZ_, int NTH_>
__global__ __launch_bounds__(NTH_, 1)
void lorenz96_kernel(const float* __restrict__ X0,
                     const float* __restrict__ Y0,
                     const float* __restrict__ coupling,
                     const float* __restrict__ pF,
                     const float* __restrict__ ph,
                     const float* __restrict__ pc,
                     const float* __restrict__ pdt,
                     float* __restrict__ xhist,
                     float* __restrict__ yhist)
{
    constexpr int CHUNK_ = NYV / CSZ_;            // owned cells per CTA (== NTH_)
    constexpr int EXT_   = GL + CHUNK_ + GR;

    __shared__ float sYe[2][EXT_ + 3];            // 1 left pad + EXT + 2 right pads
    __shared__ float sX [2][KXV];
    __shared__ float mbxL[2][GL];
    __shared__ float mbxR[2][GR];
    __shared__ __align__(8) unsigned long long mbarL[2];
    __shared__ __align__(8) unsigned long long mbarR[2];

    const int t = threadIdx.x;
    const bool isX = (t < KXV);

    uint32_t rank;
    asm("mov.u32 %0, %%cluster_ctarank;" : "=r"(rank));
    const uint32_t lrank = (rank + CSZ_ - 1) % CSZ_;
    const uint32_t rrank = (rank + 1) % CSZ_;

    const float F  = *pF;
    const float h  = *ph;
    const float c  = *pc;
    const float dt = *pdt;

    // frozen bit-exact constant recipe
    const float a      = __fmul_rn(__fmul_rn(-1.0f, c), 32.0f);
    const float hcJ    = __fdiv_rn(__fmul_rn(h, c), 32.0f);
    const float halfdt = __fmul_rn(0.5f, dt);
    const float dt6    = __fdiv_rn(dt, 6.0f);

    const int jg  = (int)rank * CHUNK_ + t;
    const int xiO = jg >> 5;
    const int xo  = GL + t;

    // ghost duty: threads [GBASE, GBASE+NG)
    const bool hasG = (t >= GBASE) && (t < GBASE + NG);
    const int  gi   = t - GBASE;
    const int  gx   = hasG ? ((gi < GL) ? gi : (GL + CHUNK_ + (gi - GL))) : 0;
    const int  gg   = ((int)rank * CHUNK_ + gx - GL + NYV) & (NYV - 1);
    const int  xiG  = gg >> 5;

    if (t == 0) {
        #pragma unroll
        for (int b = 0; b < 2; b++) {
            mbar_init(s2u(&mbarL[b]), GL);
            mbar_init(s2u(&mbarR[b]), GR);
        }
        sYe[0][0] = 0.f;         sYe[1][0] = 0.f;
        sYe[0][EXT_+1] = 0.f;    sYe[1][EXT_+1] = 0.f;
        sYe[0][EXT_+2] = 0.f;    sYe[1][EXT_+2] = 0.f;
    }
    __syncthreads();
    asm volatile("barrier.cluster.arrive.aligned;" ::: "memory");
    asm volatile("barrier.cluster.wait.aligned;"   ::: "memory");

    uint32_t raR_d = 0, raR_b = 0, raL_d = 0, raL_b = 0;
    if (t < GR) {
        raR_d = mapa_u32(s2u(&mbxR[0][t]), lrank);
        raR_b = mapa_u32(s2u(&mbarR[0]),   lrank);
    }
    if (t >= CHUNK_ - GL) {
        raL_d = mapa_u32(s2u(&mbxL[0][t - (CHUNK_ - GL)]), rrank);
        raL_b = mapa_u32(s2u(&mbarL[0]),                   rrank);
    }

    // ---- state init (row 0) ----
    float yb = Y0[jg];
    float yc = yb, d1 = 0.f, d2 = 0.f;
    yhist[jg] = yb;
    sYe[0][xo + 1] = yb;

    float gyb = 0.f, gyc = 0.f, gd1 = 0.f, gd2 = 0.f;
    if (hasG) {
        gyb = Y0[gg];
        gyc = gyb;
        sYe[0][gx + 1] = gyb;
    }

    float xb = 0.f, xc = 0.f, xd1 = 0.f, xd2 = 0.f, coup_next = 0.f;
    if (isX) {
        xb = X0[t]; xc = xb;
        sX[0][t] = xb;
        coup_next = coupling[t];
        if (rank == 0) xhist[t] = xb;
    }
    __syncthreads();

    int xrnd = 0;

    for (int n = 1; n < NTS; n++) {
        const float coup = coup_next;
        if (isX && n < NTS - 1) coup_next = coupling[n * KXV + t];

        #pragma unroll
        for (int s = 0; s < 4; s++) {
            const int rb = s & 1;
            const int wb = rb ^ 1;

            // owned cell derivative
            const float ym1 = sYe[rb][xo];
            const float yp1 = sYe[rb][xo + 2];
            const float yp2 = sYe[rb][xo + 3];
            const float xs  = sX[rb][xiO];
            const float t1 = __fsub_rn(yp2, ym1);
            const float t2 = __fmul_rn(a, yp1);
            const float t4 = __fmul_rn(c, yc);
            const float t5 = __fmaf_rn(t2, t1, -t4);
            const float dn = __fmaf_rn(hcJ, xs, t5);

            // ghost cell derivative
            float gdn = 0.f;
            if (hasG) {
                const float gm1 = sYe[rb][gx];
                const float gp1 = sYe[rb][gx + 2];
                const float gp2 = sYe[rb][gx + 3];
                const float gxs = sX[rb][xiG];
                const float g1 = __fsub_rn(gp2, gm1);
                const float g2 = __fmul_rn(a, gp1);
                const float g4 = __fmul_rn(c, gyc);
                const float g5 = __fmaf_rn(g2, g1, -g4);
                gdn = __fmaf_rn(hcJ, gxs, g5);
            }

            // X derivative
            float xdn = 0.f;
            if (isX) {
                const float xm2 = sX[rb][(t + KXV - 2) & (KXV - 1)];
                const float xm1 = sX[rb][(t + KXV - 1) & (KXV - 1)];
                const float xp1 = sX[rb][(t + 1) & (KXV - 1)];
                const float u1 = __fsub_rn(xp1, xm2);
                const float u3 = __fmaf_rn(xm1, u1, -xc);
                const float u4 = __fadd_rn(u3, F);
                xdn = __fadd_rn(u4, coup);
            }

            // stage updates (frozen recipe)
            if (s == 0) {
                d1 = dn;                        yc  = __fmaf_rn(halfdt, dn,  yb);
                if (hasG) { gd1 = gdn;          gyc = __fmaf_rn(halfdt, gdn, gyb); }
                if (isX)  { xd1 = xdn;          xc  = __fmaf_rn(halfdt, xdn, xb); }
            } else if (s == 1) {
                d2 = dn;                        yc  = __fmaf_rn(halfdt, dn,  yb);
                if (hasG) { gd2 = gdn;          gyc = __fmaf_rn(halfdt, gdn, gyb); }
                if (isX)  { xd2 = xdn;          xc  = __fmaf_rn(halfdt, xdn, xb); }
            } else if (s == 2) {
                d2 = __fadd_rn(d2, dn);         yc  = __fmaf_rn(dt, dn,  yb);
                if (hasG) { gd2 = __fadd_rn(gd2, gdn); gyc = __fmaf_rn(dt, gdn, gyb); }
                if (isX)  { xd2 = __fadd_rn(xd2, xdn); xc  = __fmaf_rn(dt, xdn, xb); }
            } else {
                const float sA  = __fadd_rn(d1, dn);
                const float sum = __fmaf_rn(2.0f, d2, sA);
                yc = __fmaf_rn(dt6, sum, yb);  yb = yc;
                if (hasG) {
                    const float gA  = __fadd_rn(gd1, gdn);
                    const float gsm = __fmaf_rn(2.0f, gd2, gA);
                    gyc = __fmaf_rn(dt6, gsm, gyb);  gyb = gyc;
                }
                if (isX) {
                    const float xA  = __fadd_rn(xd1, xdn);
                    const float xsm = __fmaf_rn(2.0f, xd2, xA);
                    xc = __fmaf_rn(dt6, xsm, xb);  xb = xc;
                }
            }

            sYe[wb][xo + 1] = yc;
            if (hasG) sYe[wb][gx + 1] = gyc;
            if (isX)  sX[wb][t] = xc;
            __syncthreads();
        }

        // history row n
        yhist[(size_t)n * NYV + jg] = yc;
        if (isX && rank == 0) xhist[(size_t)n * KXV + t] = xc;

        // ghost exchange every GSTEP steps
        if ((n & (GSTEP - 1)) == 0 && n < NTS - 1) {
            const int      buf = xrnd & 1;
            const uint32_t par = (uint32_t)((xrnd >> 1) & 1);

            if (t < GR) {
                remote_st(raR_d + (uint32_t)buf * (GR * 4), yc);
                remote_arrive(raR_b + (uint32_t)buf * 8);
            }
            if (t >= CHUNK_ - GL) {
                remote_st(raL_d + (uint32_t)buf * (GL * 4), yc);
                remote_arrive(raL_b + (uint32_t)buf * 8);
            }

            if (hasG) {
                if (gi < GL) {
                    mbar_wait(s2u(&mbarL[buf]), par);
                    gyb = mbxL[buf][gi];
                } else {
                    mbar_wait(s2u(&mbarR[buf]), par);
                    gyb = mbxR[buf][gi - GL];
                }
                gyc = gyb;
                sYe[0][gx + 1] = gyb;
            }
            xrnd++;
            __syncthreads();
        }
    }

    asm volatile("barrier.cluster.arrive.aligned;" ::: "memory");
    asm volatile("barrier.cluster.wait.aligned;"   ::: "memory");
}

extern "C" void kernel_launch(void* const* d_in, const int* in_sizes, int n_in,
                              void* d_out, int out_size)
{
    const float* X0  = (const float*)d_in[0];
    const float* Y0  = (const float*)d_in[1];
    const float* cp  = (const float*)d_in[2];
    const float* pF  = (const float*)d_in[3];
    const float* ph  = (const float*)d_in[4];
    // d_in[5] = b (unused by the math)
    const float* pc  = (const float*)d_in[6];
    const float* pdt = (const float*)d_in[7];

    float* out   = (float*)d_out;
    float* xhist = out;                       // [2048, 256]
    float* yhist = out + (size_t)NTS * KXV;   // [2048, 8192]

    // Try a 16-CTA nonportable cluster (512 threads, 512 Y/CTA); fall back to
    // the proven 8-CTA/1024-thread configuration if unsupported.
    cudaLaunchAttribute attrs[1];
    attrs[0].id = cudaLaunchAttributeClusterDimension;

    bool use16 = false;
    {
        cudaError_t e = cudaFuncSetAttribute(
            lorenz96_kernel<16, 512>,
            cudaFuncAttributeNonPortableClusterSizeAllowed, 1);
        if (e == cudaSuccess) {
            cudaLaunchConfig_t probe = {};
            probe.gridDim  = {16, 1, 1};
            probe.blockDim = {512, 1, 1};
            attrs[0].val.clusterDim = {16, 1, 1};
            probe.attrs = attrs;
            probe.numAttrs = 1;
            int nclu = 0;
            e = cudaOccupancyMaxActiveClusters(&nclu, lorenz96_kernel<16, 512>, &probe);
            use16 = (e == cudaSuccess && nclu >= 1);
        }
        cudaGetLastError();   // clear any probe error state
    }

    if (use16) {
        cudaLaunchConfig_t cfg = {};
        cfg.gridDim  = {16, 1, 1};
        cfg.blockDim = {512, 1, 1};
        attrs[0].val.clusterDim = {16, 1, 1};
        cfg.attrs = attrs;
        cfg.numAttrs = 1;
        cudaLaunchKernelEx(&cfg, lorenz96_kernel<16, 512>,
                           X0, Y0, cp, pF, ph, pc, pdt, xhist, yhist);
    } else {
        cudaLaunchConfig_t cfg = {};
        cfg.gridDim  = {8, 1, 1};
        cfg.blockDim = {1024, 1, 1};
        attrs[0].val.clusterDim = {8, 1, 1};
        cfg.attrs = attrs;
        cfg.numAttrs = 1;
        cudaLaunchKernelEx(&cfg, lorenz96_kernel<8, 1024>,
                           X0, Y0, cp, pF, ph, pc, pdt, xhist, yhist);
    }
}